// round 3
// baseline (speedup 1.0000x reference)
#include <cuda_runtime.h>

// Spatial correlation: out[b, di*9+dj, i, j] = (1/256) * sum_c x[b,c,i,j] * y[b,c,i+di-4, j+dj-4]
// x,y: [16, 256, 64, 64] f32, zero padding outside image.
//
// Strategy: register-blocked CUDA-core kernel.
//   Thread owns 4 j-pixels x 3 di x 9 dj = 108 fp32 accumulators.
//   Per channel per di: 12-float y strip (3x LDS.128) feeds 36 FFMAs -> 1.33 B/MAC smem.
//   Block: 8x64 pixel tile (full image width), 384 threads = 16 jg x 3 dg x 8 ti.
//   Double-buffered smem y halo tile (16x72), register prefetch of next channel,
//   one __syncthreads per channel.

#define TI 8
#define SROWS 16   // TI + 8 halo rows
#define SCOLS 72   // 64 + 8 halo cols
#define NTHREADS 384

__global__ __launch_bounds__(NTHREADS, 1)
void corr_kernel(const float* __restrict__ x,
                 const float* __restrict__ y,
                 float* __restrict__ out) {
    __shared__ float ys[2][SROWS][SCOLS];

    const int tid = threadIdx.x;
    const int jg  = tid & 15;         // 0..15 : j-group (4 pixels)
    const int dg  = (tid >> 4) % 3;   // 0..2  : di-group (3 di values)
    const int ti  = tid / 48;         // 0..7  : row within tile
    const int b   = blockIdx.y;       // batch
    const int gi0 = blockIdx.x * TI;  // first output row of tile
    const int i   = gi0 + ti;
    const int j0  = jg * 4;

    const size_t bbase = (size_t)b * 256 * 64 * 64;
    const float* xb = x + bbase;
    const float* yb = y + bbase;

    // Cooperative y staging: SROWS*SCOLS = 1152 = 3 * 384 elements.
    int  lrow[3], lcol[3], lidx[3];
    bool lok[3];
#pragma unroll
    for (int k = 0; k < 3; k++) {
        int idx = tid + k * NTHREADS;
        int r  = idx / SCOLS;
        int cc = idx - r * SCOLS;
        lrow[k] = r; lcol[k] = cc;
        int gr = gi0 - 4 + r;
        int gc = cc - 4;
        lok[k]  = (gr >= 0) && (gr < 64) && (gc >= 0) && (gc < 64);
        lidx[k] = gr * 64 + gc;
    }

    float acc[3][9][4];
#pragma unroll
    for (int l = 0; l < 3; l++)
#pragma unroll
        for (int d = 0; d < 9; d++)
#pragma unroll
            for (int q = 0; q < 4; q++) acc[l][d][q] = 0.0f;

    // Preload channel 0
    float ycur[3];
#pragma unroll
    for (int k = 0; k < 3; k++)
        ycur[k] = lok[k] ? yb[lidx[k]] : 0.0f;
    float4 xcur = *(const float4*)(xb + (size_t)i * 64 + j0);

#pragma unroll
    for (int k = 0; k < 3; k++)
        ys[0][lrow[k]][lcol[k]] = ycur[k];
    __syncthreads();

    for (int c = 0; c < 256; c++) {
        const int buf = c & 1;

        // Prefetch next channel into registers (overlaps with compute below)
        float  ynext[3];
        float4 xnext = xcur;
        if (c < 255) {
            const float* ybn = yb + (size_t)(c + 1) * 4096;
#pragma unroll
            for (int k = 0; k < 3; k++)
                ynext[k] = lok[k] ? ybn[lidx[k]] : 0.0f;
            xnext = *(const float4*)(xb + (size_t)(c + 1) * 4096 + i * 64 + j0);
        }

        // Compute: 3 di x (3 LDS.128 + 36 FFMA)
#pragma unroll
        for (int l = 0; l < 3; l++) {
            const int di   = dg * 3 + l;
            const int srow = ti + di;  // (i + di - 4) - (gi0 - 4)
            const float* yr = &ys[buf][srow][j0];
            float4 w0 = *(const float4*)(yr + 0);
            float4 w1 = *(const float4*)(yr + 4);
            float4 w2 = *(const float4*)(yr + 8);
            float wv[12] = {w0.x, w0.y, w0.z, w0.w,
                            w1.x, w1.y, w1.z, w1.w,
                            w2.x, w2.y, w2.z, w2.w};
#pragma unroll
            for (int d = 0; d < 9; d++) {
                acc[l][d][0] += xcur.x * wv[d + 0];
                acc[l][d][1] += xcur.y * wv[d + 1];
                acc[l][d][2] += xcur.z * wv[d + 2];
                acc[l][d][3] += xcur.w * wv[d + 3];
            }
        }

        // Stage next channel into the other buffer
        if (c < 255) {
#pragma unroll
            for (int k = 0; k < 3; k++)
                ys[buf ^ 1][lrow[k]][lcol[k]] = ynext[k];
            xcur = xnext;
        }
        __syncthreads();
    }

    // Epilogue: scale by 1/256, vectorized stores
    const float scale = 1.0f / 256.0f;
    float* ob = out + (size_t)b * 81 * 4096;
#pragma unroll
    for (int l = 0; l < 3; l++) {
        const int di = dg * 3 + l;
#pragma unroll
        for (int d = 0; d < 9; d++) {
            const int p = di * 9 + d;
            float4 v;
            v.x = acc[l][d][0] * scale;
            v.y = acc[l][d][1] * scale;
            v.z = acc[l][d][2] * scale;
            v.w = acc[l][d][3] * scale;
            *(float4*)(ob + (size_t)p * 4096 + i * 64 + j0) = v;
        }
    }
}

extern "C" void kernel_launch(void* const* d_in, const int* in_sizes, int n_in,
                              void* d_out, int out_size) {
    const float* x = (const float*)d_in[0];
    const float* y = (const float*)d_in[1];
    float* out = (float*)d_out;
    dim3 grid(8, 16);   // 8 i-tiles x 16 batches
    corr_kernel<<<grid, NTHREADS>>>(x, y, out);
}

// round 5
// speedup vs baseline: 1.6988x; 1.6988x over previous
#include <cuda_runtime.h>

// Spatial correlation: out[b, di*9+dj, i, j] = (1/256) * sum_c x[b,c,i,j] * y[b,c,i+di-4, j+dj-4]
// x,y: [16, 256, 64, 64] f32, zero padding outside image.
//
// Round-3 design: cp.async 4-stage pipeline, thin thread tile.
//   Thread: 4 j-pixels x 1 di x 9 dj = 36 fp32 accumulators (~70 regs).
//   Block: 576 threads = 16 jg x 9 dg x 4 ti, tile = 4 rows x 64 cols.
//   Grid: 16 i-tiles x 16 batches = 256 blocks.
//   Smem ring: 4 stages x 2 channels x (y halo tile 12x72 + x tile 4x64).
//   Zero padding via cp.async src-size=0 zero-fill (halo chunks are 16B-granular).

#define TI       4
#define SROWS    12            // TI + 8 halo rows
#define SCOLS    72            // 64 + 8 halo cols
#define YF       (SROWS * SCOLS)   // 864 floats per channel (y tile)
#define XF       (TI * 64)         // 256 floats per channel (x tile)
#define CPS      2                 // channels per stage
#define STAGE_F  (CPS * (YF + XF)) // 2240 floats per stage
#define STAGES   4
#define NTHREADS 576
#define NCHUNK   (CPS * (YF / 4 + XF / 4))  // 560 16B chunks per stage
#define NSTAGE_TOT 128             // 256 channels / CPS

__device__ __forceinline__ void cp16(unsigned saddr, const float* g, int nbytes) {
    asm volatile("cp.async.ca.shared.global [%0], [%1], 16, %2;\n"
                 :: "r"(saddr), "l"(g), "r"(nbytes));
}

__global__ __launch_bounds__(NTHREADS, 1)
void corr_kernel(const float* __restrict__ x,
                 const float* __restrict__ y,
                 float* __restrict__ out) {
    __shared__ float sm[STAGES * STAGE_F];   // 35840 B

    const int tid = threadIdx.x;
    const int jg  = tid & 15;          // 0..15 : j-group (4 pixels)
    const int dg  = (tid >> 4) % 9;    // 0..8  : di
    const int ti  = tid / 144;         // 0..3  : row within tile
    const int b   = blockIdx.y;
    const int gi0 = blockIdx.x * TI;
    const int j0  = jg * 4;

    const size_t bbase = (size_t)b * 256 * 4096;
    const float* xb = x + bbase;
    const float* yb = y + bbase;

    // ---- per-thread chunk assignment (computed once) ----
    // stage float layout: [y ch0 : 864][y ch1 : 864][x ch0 : 256][x ch1 : 256]
    const bool active = tid < NCHUNK;
    const float* gbase = yb;
    long goff = 0;          // element offset within a channel plane
    int  sdst_f = 0;        // float offset within a stage
    int  nbytes = 0;
    int  lch = 0;           // which of the 2 channels in the stage
    if (active) {
        lch = tid / (NCHUNK / 2);        // 0 or 1
        int mm = tid % (NCHUNK / 2);     // 0..279
        if (mm < YF / 4) {               // y chunk
            int r  = mm / (SCOLS / 4);   // 0..11
            int cc = (mm % (SCOLS / 4)) * 4;  // 0,4,...,68
            int gr = gi0 - 4 + r;
            bool ok = (gr >= 0) && (gr < 64) && (cc >= 4) && (cc <= 64);
            nbytes = ok ? 16 : 0;
            gbase  = yb;
            goff   = ok ? (long)(gr * 64 + (cc - 4)) : 0;
            sdst_f = lch * YF + r * SCOLS + cc;
        } else {                         // x chunk
            int mm2 = mm - YF / 4;       // 0..63
            int r   = mm2 / 16;          // 0..3
            int cc  = (mm2 % 16) * 4;    // 0..60
            nbytes  = 16;
            gbase   = xb;
            goff    = (long)((gi0 + r) * 64 + cc);
            sdst_f  = 2 * YF + lch * XF + r * 64 + cc;
        }
    }
    const unsigned smbase = (unsigned)__cvta_generic_to_shared(sm);

    float acc[9][4];
#pragma unroll
    for (int d = 0; d < 9; d++)
#pragma unroll
        for (int q = 0; q < 4; q++) acc[d][q] = 0.0f;

    // ---- prologue: stages 0..2 in flight ----
#pragma unroll
    for (int s = 0; s < STAGES - 1; s++) {
        if (active)
            cp16(smbase + (unsigned)((s % STAGES) * STAGE_F + sdst_f) * 4u,
                 gbase + goff + (size_t)(CPS * s + lch) * 4096, nbytes);
        asm volatile("cp.async.commit_group;\n" ::: "memory");
    }

    // ---- main loop over 128 stages (256 channels) ----
    for (int s = 0; s < NSTAGE_TOT; s++) {
        asm volatile("cp.async.wait_group 2;\n" ::: "memory");
        __syncthreads();

        // refill buffer (s+3)%4 == (s-1)%4 : safe, all warps finished stage s-1
        if (s + STAGES - 1 < NSTAGE_TOT && active)
            cp16(smbase + (unsigned)(((s + STAGES - 1) % STAGES) * STAGE_F + sdst_f) * 4u,
                 gbase + goff + (size_t)(CPS * (s + STAGES - 1) + lch) * 4096, nbytes);
        asm volatile("cp.async.commit_group;\n" ::: "memory");

        const float* st = sm + (s & (STAGES - 1)) * STAGE_F;
#pragma unroll
        for (int ch = 0; ch < CPS; ch++) {
            const float* ybuf = st + ch * YF;
            const float* xbuf = st + 2 * YF + ch * XF;
            float4 xv = *(const float4*)(xbuf + ti * 64 + j0);
            const float* yr = ybuf + (ti + dg) * SCOLS + j0;
            float4 w0 = *(const float4*)(yr + 0);
            float4 w1 = *(const float4*)(yr + 4);
            float4 w2 = *(const float4*)(yr + 8);
            float wv[12] = {w0.x, w0.y, w0.z, w0.w,
                            w1.x, w1.y, w1.z, w1.w,
                            w2.x, w2.y, w2.z, w2.w};
#pragma unroll
            for (int d = 0; d < 9; d++) {
                acc[d][0] += xv.x * wv[d + 0];
                acc[d][1] += xv.y * wv[d + 1];
                acc[d][2] += xv.z * wv[d + 2];
                acc[d][3] += xv.w * wv[d + 3];
            }
        }
    }

    // ---- epilogue: scale, vectorized coalesced stores ----
    const float scale = 1.0f / 256.0f;
    float* ob = out + (size_t)b * 81 * 4096;
    const int i = gi0 + ti;
#pragma unroll
    for (int d = 0; d < 9; d++) {
        const int p = dg * 9 + d;
        float4 v;
        v.x = acc[d][0] * scale;
        v.y = acc[d][1] * scale;
        v.z = acc[d][2] * scale;
        v.w = acc[d][3] * scale;
        *(float4*)(ob + (size_t)p * 4096 + i * 64 + j0) = v;
    }
}

extern "C" void kernel_launch(void* const* d_in, const int* in_sizes, int n_in,
                              void* d_out, int out_size) {
    const float* x = (const float*)d_in[0];
    const float* y = (const float*)d_in[1];
    float* out = (float*)d_out;
    dim3 grid(16, 16);   // 16 i-tiles x 16 batches
    corr_kernel<<<grid, NTHREADS>>>(x, y, out);
}